// round 17
// baseline (speedup 1.0000x reference)
#include <cuda_runtime.h>
#include <cuda_bf16.h>
#include <cstdint>
#include <math.h>

// MySimpleRNN: h_t = tanh(x_t@wx + h_{t-1}@wh + b), 64 steps, h_final[4096,512].
// R16 (= R15 resubmit after infra failure): fused per-step kernel (R8 structure)
// with the recurrent GEMM converted to dual-limb INT8 (mma.m16n8k32.s8.s32):
//   h = (a1*2^7 + a0)/2^14 ,  wh = (b1*2^7 + b0)/2^17   (balanced limbs)
//   pre = P2*2^-17 + P1*2^-24,  P2=sum a1b1, P1=sum(a1b0+a0b1)  (a0b0 dropped)
// Exact s32 accumulation; 2x fewer tensor instructions on the sequential path.
// x-projection chunks stay bf16 split-precision (hi*hi+hi*lo+lo*hi), fp32 acc.

#define NF 128
#define NH 512
#define TT 64
#define BMAX 4096

#define BM 128
#define BN 128
#define KC 64
#define NTHREADS 256     // 8 warps: 4(M) x 2(N), warp tile 32x64

#define STAGE_BYTES 65536u   // 4 quadrants x 16KB
#define SMEM_BYTES (2 * STAGE_BYTES)

// ---------------- scratch (device globals; no allocation) ----------------
__device__ __align__(1024) char g_h1[2][(size_t)BMAX * NH];   // h hi limb (s8)
__device__ __align__(1024) char g_h0[2][(size_t)BMAX * NH];   // h lo limb (s8)
__device__ __align__(1024) char g_whT1[(size_t)NH * NH];      // wh^T [n][k] hi limb
__device__ __align__(1024) char g_whT0[(size_t)NH * NH];      // wh^T [n][k] lo limb
__device__ __align__(1024) __nv_bfloat16 g_xhi[TT][(size_t)BMAX * NF];
__device__ __align__(1024) __nv_bfloat16 g_xlo[TT][(size_t)BMAX * NF];
__device__ __align__(1024) __nv_bfloat16 g_wx_hi[NF * NH];    // [k][n]
__device__ __align__(1024) __nv_bfloat16 g_wx_lo[NF * NH];

// ---------------- helpers ----------------
__device__ __forceinline__ uint32_t smem_u32(const void* p) {
    uint32_t a;
    asm("{ .reg .u64 t; cvta.to.shared.u64 t, %1; cvt.u32.u64 %0, t; }" : "=r"(a) : "l"(p));
    return a;
}
__device__ __forceinline__ void ldsm_x4(uint32_t* r, uint32_t addr) {
    asm volatile("ldmatrix.sync.aligned.m8n8.x4.shared.b16 {%0,%1,%2,%3}, [%4];"
                 : "=r"(r[0]), "=r"(r[1]), "=r"(r[2]), "=r"(r[3]) : "r"(addr));
}
__device__ __forceinline__ void ldsm_x4_t(uint32_t* r, uint32_t addr) {
    asm volatile("ldmatrix.sync.aligned.m8n8.x4.trans.shared.b16 {%0,%1,%2,%3}, [%4];"
                 : "=r"(r[0]), "=r"(r[1]), "=r"(r[2]), "=r"(r[3]) : "r"(addr));
}
__device__ __forceinline__ uint32_t lds32(uint32_t addr) {
    uint32_t v;
    asm volatile("ld.shared.b32 %0, [%1];" : "=r"(v) : "r"(addr));
    return v;
}
__device__ __forceinline__ void mma16816(float* d, const uint32_t* a, const uint32_t* b) {
    asm volatile(
        "mma.sync.aligned.m16n8k16.row.col.f32.bf16.bf16.f32 "
        "{%0,%1,%2,%3}, {%4,%5,%6,%7}, {%8,%9}, {%0,%1,%2,%3};"
        : "+f"(d[0]), "+f"(d[1]), "+f"(d[2]), "+f"(d[3])
        : "r"(a[0]), "r"(a[1]), "r"(a[2]), "r"(a[3]), "r"(b[0]), "r"(b[1]));
}
__device__ __forceinline__ void mma_s8(int* d, const uint32_t* a, const uint32_t* b) {
    asm volatile(
        "mma.sync.aligned.m16n8k32.row.col.s32.s8.s8.s32 "
        "{%0,%1,%2,%3}, {%4,%5,%6,%7}, {%8,%9}, {%0,%1,%2,%3};"
        : "+r"(d[0]), "+r"(d[1]), "+r"(d[2]), "+r"(d[3])
        : "r"(a[0]), "r"(a[1]), "r"(a[2]), "r"(a[3]), "r"(b[0]), "r"(b[1]));
}
__device__ __forceinline__ void cp_async16(uint32_t dst, const void* src) {
    asm volatile("cp.async.cg.shared.global [%0], [%1], 16;" :: "r"(dst), "l"(src) : "memory");
}
#define CP_COMMIT() asm volatile("cp.async.commit_group;" ::: "memory")
#define CP_WAIT(n)  asm volatile("cp.async.wait_group %0;" :: "n"(n) : "memory")

__device__ __forceinline__ uint32_t pack_bf16x2(float a, float b) {
    __nv_bfloat16 ha = __float2bfloat16(a);
    __nv_bfloat16 hb = __float2bfloat16(b);
    return ((uint32_t)__bfloat16_as_ushort(hb) << 16) | (uint32_t)__bfloat16_as_ushort(ha);
}

// ---------------- precompute ----------------
__global__ void prep_weights(const float* __restrict__ wx, const float* __restrict__ wh) {
    int idx = blockIdx.x * blockDim.x + threadIdx.x;
    if (idx < NH * NH) {
        int k = idx / NH, n = idx % NH;
        int q = __float2int_rn(wh[idx] * 131072.0f);       // 2^17, |wh|<=0.0765 -> |q|<=10035
        int b1 = (q + 64) >> 7;                            // balanced: b0 in [-64,63]
        int b0 = q - (b1 << 7);
        g_whT1[(size_t)n * NH + k] = (char)b1;
        g_whT0[(size_t)n * NH + k] = (char)b0;
    }
    if (idx < NF * NH) {
        float v = wx[idx];
        __nv_bfloat16 hi = __float2bfloat16(v);
        g_wx_hi[idx] = hi;
        g_wx_lo[idx] = __float2bfloat16(v - __bfloat162float(hi));
    }
}

__global__ void prep_x(const float* __restrict__ x, int B) {
    size_t idx = (size_t)blockIdx.x * blockDim.x + threadIdx.x;
    if (idx < (size_t)B * TT * NF) {
        int f = (int)(idx % NF);
        size_t r = idx / NF;
        int t = (int)(r % TT);
        size_t b = r / TT;
        float v = x[idx];
        __nv_bfloat16 hi = __float2bfloat16(v);
        g_xhi[t][b * NF + f] = hi;
        g_xlo[t][b * NF + f] = __float2bfloat16(v - __bfloat162float(hi));
    }
}

// ---------------- step kernel ----------------
// Stage layout (64KB): q0 A1/Ahi | q1 A0/Alo | q2 B1/Bhi | q3 B0/Blo.
// s8 tiles: 128 rows x 64B data, padded to 128B row stride (swizzled).
// bf16 A: 128 rows x 128B; bf16 B: 64 rows x 256B.

__global__ __launch_bounds__(NTHREADS, 1)
void rnn_step(const float* __restrict__ bias, float* __restrict__ dout, int t)
{
    extern __shared__ __align__(1024) char smem[];
    const uint32_t sbase = smem_u32(smem);
    const int tid = threadIdx.x;
    const int wid = tid >> 5;
    const int lid = tid & 31;
    const int wm = wid & 3, wn = wid >> 2;   // 4(M) x 2(N), warp tile 32x64
    const int m0 = blockIdx.y * BM;
    const int n0 = blockIdx.x * BN;
    const int src = (t + 1) & 1;
    const int dst = t & 1;

    const int nrec = (t > 0) ? (NH / KC) : 0;   // 8 s8 chunks
    const int nchunks = nrec + NF / KC;          // + 2 bf16 x chunks

    const char* hA1 = g_h1[src] + (size_t)m0 * NH;
    const char* hA0 = g_h0[src] + (size_t)m0 * NH;
    const __nv_bfloat16* xAhi = g_xhi[t] + (size_t)m0 * NF;
    const __nv_bfloat16* xAlo = g_xlo[t] + (size_t)m0 * NF;

    // ---- s8 recurrent chunk loader: A limbs [128][64B], B^T limbs [128][64B] ----
    auto load_h_chunk = [&](int kbase, uint32_t sb) {
#pragma unroll
        for (int j = 0; j < 2; ++j) {            // A limbs: 512 segs each
            int seg = j * 256 + tid;
            uint32_t row = (uint32_t)(seg >> 2);
            uint32_t ch = (uint32_t)(seg & 3);
            uint32_t off = row * 128u + ((ch ^ (row & 7u)) << 4);
            cp_async16(sb + off,          hA1 + (size_t)row * NH + kbase + ch * 16);
            cp_async16(sb + 16384u + off, hA0 + (size_t)row * NH + kbase + ch * 16);
        }
#pragma unroll
        for (int j = 0; j < 2; ++j) {            // B^T limbs: 512 segs each
            int seg = j * 256 + tid;
            uint32_t n = (uint32_t)(seg >> 2);
            uint32_t ch = (uint32_t)(seg & 3);
            uint32_t off = n * 128u + ((ch ^ (n & 7u)) << 4);
            cp_async16(sb + 32768u + off, g_whT1 + (size_t)(n0 + n) * NH + kbase + ch * 16);
            cp_async16(sb + 49152u + off, g_whT0 + (size_t)(n0 + n) * NH + kbase + ch * 16);
        }
        CP_COMMIT();
    };

    // ---- bf16 x chunk loader (R8) ----
    auto load_x_chunk = [&](int kbase, uint32_t sb) {
#pragma unroll
        for (int j = 0; j < 4; ++j) {
            int seg = j * 256 + tid;
            uint32_t row = (uint32_t)(seg >> 3);
            uint32_t ch = (uint32_t)(seg & 7);
            uint32_t off = row * 128u + ((ch ^ (row & 7u)) << 4);
            cp_async16(sb + off,          xAhi + (size_t)row * NF + kbase + ch * 8);
            cp_async16(sb + 16384u + off, xAlo + (size_t)row * NF + kbase + ch * 8);
        }
#pragma unroll
        for (int j = 0; j < 4; ++j) {
            int seg = j * 256 + tid;
            uint32_t kr = (uint32_t)(seg >> 4);
            uint32_t ch = (uint32_t)(seg & 15);
            uint32_t off = kr * 256u + ((ch ^ (kr & 7u)) << 4);
            cp_async16(sb + 32768u + off, g_wx_hi + (size_t)(kbase + kr) * NH + n0 + ch * 8);
            cp_async16(sb + 49152u + off, g_wx_lo + (size_t)(kbase + kr) * NH + n0 + ch * 8);
        }
        CP_COMMIT();
    };

    auto load_chunk = [&](int c, int buf) {
        uint32_t sb = sbase + (uint32_t)buf * STAGE_BYTES;
        if (c < nrec) load_h_chunk(c * KC, sb);
        else          load_x_chunk((c - nrec) * KC, sb);
    };

    int P2[2][8][4], P1[2][8][4];
    float acc[2][8][4];
#pragma unroll
    for (int i = 0; i < 2; ++i)
#pragma unroll
        for (int j = 0; j < 8; ++j)
#pragma unroll
            for (int q = 0; q < 4; ++q) { P2[i][j][q] = 0; P1[i][j][q] = 0; }

    load_chunk(0, 0);
    load_chunk(1, 1);

#pragma unroll 1
    for (int i = 0; i < nchunks; ++i) {
        if (i + 1 < nchunks) CP_WAIT(1); else CP_WAIT(0);
        __syncthreads();
        const uint32_t sb = sbase + (uint32_t)(i & 1) * STAGE_BYTES;

        if (i < nrec) {
            // ---- s8 compute: 2 k32 iterations ----
            const uint32_t sA1 = sb, sA0 = sb + 16384u, sB1 = sb + 32768u, sB0 = sb + 49152u;
#pragma unroll
            for (int kk2 = 0; kk2 < 2; ++kk2) {
                uint32_t a1[2][4], a0[2][4];
#pragma unroll
                for (int mt = 0; mt < 2; ++mt) {
                    uint32_t row = (uint32_t)(wm * 32 + mt * 16 + ((lid >> 3) & 1) * 8 + (lid & 7));
                    uint32_t kc = (uint32_t)(kk2 * 2 + (lid >> 4));
                    uint32_t off = row * 128u + ((kc ^ (row & 7u)) << 4);
                    ldsm_x4(a1[mt], sA1 + off);
                    ldsm_x4(a0[mt], sA0 + off);
                }
                // B fragments via LDS.32 from B^T [n][k]
                const uint32_t nbase = (uint32_t)(wn * 64 + (lid >> 2));
                const uint32_t kb = (uint32_t)(4 * (lid & 3));
                const uint32_t ch0 = (uint32_t)(kk2 * 2);
#pragma unroll
                for (int nt = 0; nt < 8; ++nt) {
                    uint32_t n = nbase + nt * 8;
                    uint32_t base = n * 128u;
                    uint32_t o0 = base + ((ch0 ^ (n & 7u)) << 4) + kb;
                    uint32_t o1 = base + (((ch0 + 1u) ^ (n & 7u)) << 4) + kb;
                    uint32_t b1[2], b0[2];
                    b1[0] = lds32(sB1 + o0); b1[1] = lds32(sB1 + o1);
                    b0[0] = lds32(sB0 + o0); b0[1] = lds32(sB0 + o1);
#pragma unroll
                    for (int mt = 0; mt < 2; ++mt) {
                        mma_s8(P2[mt][nt], a1[mt], b1);
                        mma_s8(P1[mt][nt], a1[mt], b0);
                        mma_s8(P1[mt][nt], a0[mt], b1);
                    }
                }
            }
        } else {
            if (i == nrec) {
                // fold exact s32 partials into fp32 (scales are powers of 2)
                const float c2 = 7.62939453125e-6f;      // 2^-17
                const float c1 = 5.9604644775390625e-8f; // 2^-24
#pragma unroll
                for (int mt = 0; mt < 2; ++mt)
#pragma unroll
                    for (int nt = 0; nt < 8; ++nt)
#pragma unroll
                        for (int q = 0; q < 4; ++q)
                            acc[mt][nt][q] = (float)P2[mt][nt][q] * c2 + (float)P1[mt][nt][q] * c1;
            }
            // ---- bf16 x compute (R8) ----
            const uint32_t aHi = sb, aLo = sb + 16384u, bHi = sb + 32768u, bLo = sb + 49152u;
#pragma unroll
            for (int kk = 0; kk < KC / 16; ++kk) {
                const int k0 = kk * 16;
                uint32_t ah[2][4], al[2][4];
#pragma unroll
                for (int mt = 0; mt < 2; ++mt) {
                    uint32_t row = (uint32_t)(wm * 32 + mt * 16 + ((lid >> 3) & 1) * 8 + (lid & 7));
                    uint32_t kc = (uint32_t)((k0 >> 3) + (lid >> 4));
                    uint32_t off = row * 128u + ((kc ^ (row & 7u)) << 4);
                    ldsm_x4(ah[mt], aHi + off);
                    ldsm_x4(al[mt], aLo + off);
                }
                uint32_t bh[8][2], bl[8][2];
#pragma unroll
                for (int np = 0; np < 4; ++np) {
                    int g = lid >> 3;
                    uint32_t kr = (uint32_t)(k0 + (g & 1) * 8 + (lid & 7));
                    uint32_t nc = (uint32_t)(((wn * 64 + np * 16) >> 3) + (g >> 1));
                    uint32_t off = kr * 256u + ((nc ^ (kr & 7u)) << 4);
                    uint32_t r[4];
                    ldsm_x4_t(r, bHi + off);
                    bh[np * 2][0] = r[0]; bh[np * 2][1] = r[1];
                    bh[np * 2 + 1][0] = r[2]; bh[np * 2 + 1][1] = r[3];
                    ldsm_x4_t(r, bLo + off);
                    bl[np * 2][0] = r[0]; bl[np * 2][1] = r[1];
                    bl[np * 2 + 1][0] = r[2]; bl[np * 2 + 1][1] = r[3];
                }
#pragma unroll
                for (int mt = 0; mt < 2; ++mt)
#pragma unroll
                    for (int nt = 0; nt < 8; ++nt) {
                        mma16816(acc[mt][nt], ah[mt], bh[nt]);
                        mma16816(acc[mt][nt], ah[mt], bl[nt]);
                        mma16816(acc[mt][nt], al[mt], bh[nt]);
                    }
            }
        }

        __syncthreads();
        if (i + 2 < nchunks) load_chunk(i + 2, i & 1);
    }

    // ---- epilogue: tanh(acc + bias); quantize h to s8 limbs, or fp32 out at t=63 ----
    const bool last = (t == TT - 1);
    const int gq = lid >> 2, tq = lid & 3;
#pragma unroll
    for (int mt = 0; mt < 2; ++mt)
#pragma unroll
        for (int nt = 0; nt < 8; ++nt) {
            const int col = n0 + wn * 64 + nt * 8 + tq * 2;
            const float2 bv = *(const float2*)(bias + col);
            const int r0 = m0 + wm * 32 + mt * 16 + gq;
            const int r1 = r0 + 8;
            float v00 = tanhf(acc[mt][nt][0] + bv.x);
            float v01 = tanhf(acc[mt][nt][1] + bv.y);
            float v10 = tanhf(acc[mt][nt][2] + bv.x);
            float v11 = tanhf(acc[mt][nt][3] + bv.y);
            if (last) {
                *(float2*)(dout + (size_t)r0 * NH + col) = make_float2(v00, v01);
                *(float2*)(dout + (size_t)r1 * NH + col) = make_float2(v10, v11);
            } else {
                // balanced dual-limb quantization: q = h*2^14, a1=(q+64)>>7, a0=q-a1*128
                float vv[4] = {v00, v01, v10, v11};
                char q1[4], q0[4];
#pragma unroll
                for (int c = 0; c < 4; ++c) {
                    int q = __float2int_rn(vv[c] * 16384.0f);
                    q = max(-16319, min(16319, q));
                    int a1 = (q + 64) >> 7;
                    q1[c] = (char)a1;
                    q0[c] = (char)(q - (a1 << 7));
                }
                *(char2*)&g_h1[dst][(size_t)r0 * NH + col] = make_char2(q1[0], q1[1]);
                *(char2*)&g_h1[dst][(size_t)r1 * NH + col] = make_char2(q1[2], q1[3]);
                *(char2*)&g_h0[dst][(size_t)r0 * NH + col] = make_char2(q0[0], q0[1]);
                *(char2*)&g_h0[dst][(size_t)r1 * NH + col] = make_char2(q0[2], q0[3]);
            }
        }
}

// ---------------- launch ----------------
extern "C" void kernel_launch(void* const* d_in, const int* in_sizes, int n_in,
                              void* d_out, int out_size)
{
    const float* x  = (const float*)d_in[0];  // [B, 64, 128]
    const float* wx = (const float*)d_in[1];  // [128, 512]
    const float* wh = (const float*)d_in[2];  // [512, 512]
    const float* b  = (const float*)d_in[3];  // [1, 512]
    float* out = (float*)d_out;               // [B, 512]

    const int B = in_sizes[0] / (TT * NF);    // 4096

    cudaFuncSetAttribute(rnn_step, cudaFuncAttributeMaxDynamicSharedMemorySize, SMEM_BYTES);

    prep_weights<<<(NH * NH + 255) / 256, 256>>>(wx, wh);
    {
        size_t n = (size_t)B * TT * NF;
        prep_x<<<(unsigned)((n + 255) / 256), 256>>>(x, B);
    }

    dim3 grid(NH / BN, B / BM);               // (4, 32) = 128 CTAs
    for (int t = 0; t < TT; ++t) {
        rnn_step<<<grid, NTHREADS, SMEM_BYTES>>>(b, out, t);
    }
}